// round 14
// baseline (speedup 1.0000x reference)
#include <cuda_runtime.h>
#include <cuda_fp16.h>

#define W 15
#define DIM 64
#define BLK_PER_CTA 4
#define NTHREADS 128
#define EPS 1e-6f
#define PHI 0.10471975511965977f   // pi/30

typedef unsigned int u32;

__device__ __forceinline__ float shxor(float v, int m) {
    return __shfl_xor_sync(0xffffffffu, v, m, 32);
}
__device__ __forceinline__ u32 smem_u32(const void* p) {
    return (u32)__cvta_generic_to_shared(p);
}
__device__ __forceinline__ void ldsm4(u32& r0, u32& r1, u32& r2, u32& r3, u32 a) {
    asm volatile("ldmatrix.sync.aligned.m8n8.x4.shared.b16 {%0,%1,%2,%3}, [%4];"
        : "=r"(r0), "=r"(r1), "=r"(r2), "=r"(r3) : "r"(a));
}
__device__ __forceinline__ void ldsm4t(u32& r0, u32& r1, u32& r2, u32& r3, u32 a) {
    asm volatile("ldmatrix.sync.aligned.m8n8.x4.trans.shared.b16 {%0,%1,%2,%3}, [%4];"
        : "=r"(r0), "=r"(r1), "=r"(r2), "=r"(r3) : "r"(a));
}
__device__ __forceinline__ void mma16816(float* d, const u32* a, u32 b0, u32 b1,
                                         float c0, float c1, float c2, float c3) {
    asm volatile(
        "mma.sync.aligned.m16n8k16.row.col.f32.f16.f16.f32 "
        "{%0,%1,%2,%3},{%4,%5,%6,%7},{%8,%9},{%10,%11,%12,%13};"
        : "=f"(d[0]), "=f"(d[1]), "=f"(d[2]), "=f"(d[3])
        : "r"(a[0]), "r"(a[1]), "r"(a[2]), "r"(a[3]), "r"(b0), "r"(b1),
          "f"(c0), "f"(c1), "f"(c2), "f"(c3));
}
__device__ __forceinline__ u32 h2u(__half2 h) { return *(u32*)&h; }

// one 8-deep LDG.128 batch -> relu -> fp16 -> swizzled smem tile
__device__ __forceinline__ void fill_tile(const float* __restrict__ src,
                                          unsigned short* dst, int lane) {
    const float4* gp = (const float4*)src;
    float4 t[8];
    #pragma unroll
    for (int it = 0; it < 8; ++it) {
        int i4 = it * 32 + lane;
        bool ok = (it < 7) || (lane < 16);
        if (ok) t[it] = gp[i4];
    }
    #pragma unroll
    for (int it = 0; it < 8; ++it) {
        int i4 = it * 32 + lane;
        bool ok = (it < 7) || (lane < 16);
        if (ok) {
            int r = i4 >> 4, cc = i4 & 15;
            int off = r * 64 + (((cc >> 1) ^ (r & 7)) << 3) + ((cc & 1) << 2);
            float4 a = t[it];
            uint2 p;
            p.x = h2u(__floats2half2_rn(fmaxf(a.x, 0.f), fmaxf(a.y, 0.f)));
            p.y = h2u(__floats2half2_rn(fmaxf(a.z, 0.f), fmaxf(a.w, 0.f)));
            *(uint2*)&dst[off] = p;
        }
    }
}

__global__ void __launch_bounds__(NTHREADS, 8)
robust_attn_kernel(const float* __restrict__ q, const float* __restrict__ k,
                   const float* __restrict__ v, float* __restrict__ out, int G)
{
    // per-warp fp16 tiles, 16 rows x 64 halfs (row 15 zeroed), XOR-swizzled
    __shared__ __align__(16) unsigned short sQ[BLK_PER_CTA][1024];
    __shared__ __align__(16) unsigned short sK[BLK_PER_CTA][1024];
    __shared__ __align__(16) unsigned short sV[BLK_PER_CTA][1024];

    const int tid = threadIdx.x;
    const int warp = tid >> 5;
    const int lane = tid & 31;
    const int blk = blockIdx.x * BLK_PER_CTA + warp;
    if (blk >= G) return;
    const size_t base = (size_t)blk * (W * DIM);

    unsigned short* wQ = sQ[warp];
    unsigned short* wK = sK[warp];
    unsigned short* wV = sV[warp];

    // ---- zero pad row 15 ----
    if (lane < 16) {
        uint2 z = make_uint2(0u, 0u);
        *(uint2*)&wQ[15 * 64 + lane * 4] = z;
        *(uint2*)&wK[15 * 64 + lane * 4] = z;
        *(uint2*)&wV[15 * 64 + lane * 4] = z;
    }

    // ---- fill: 3 batches of 8 LDG.128 (32-reg temps each) ----
    fill_tile(q + base, wQ, lane);
    fill_tile(k + base, wK, lane);
    fill_tile(v + base, wV, lane);

    // ---- per-lane reweight constants (zero encodes causality & j=15 pad) ----
    const int r0 = lane >> 2;
    const int jb = (lane & 3) * 2;
    float coef[2][4];
    #pragma unroll
    for (int rh = 0; rh < 2; ++rh) {
        int i = r0 + rh * 8;
        #pragma unroll
        for (int jj = 0; jj < 4; ++jj) {
            int j = jb + (jj & 1) + (jj >> 1) * 8;
            int dlt = i - j;
            coef[rh][jj] = (dlt >= 0 && j < W) ? __cosf((float)dlt * PHI) : 0.f;
        }
    }

    __syncwarp();

    const u32 qb = smem_u32(wQ), kb = smem_u32(wK), vb = smem_u32(wV);

    // ---- scores: S(16x16) = Q K^T, two n8 tiles, f32 accum ----
    float S0[4] = {0.f, 0.f, 0.f, 0.f};
    float S1[4] = {0.f, 0.f, 0.f, 0.f};
    #pragma unroll
    for (int kc = 0; kc < 4; ++kc) {
        u32 aq[4], bk[4];
        {   // A: lanes 0-15 rows 0-15 chunk 2kc; lanes 16-31 chunk 2kc+1
            int row = lane & 15;
            int ch = 2 * kc + (lane >> 4);
            ldsm4(aq[0], aq[1], aq[2], aq[3], qb + row * 128 + ((ch ^ (row & 7)) << 4));
        }
        {   // B(K): lanes 0-7 r0-7 lo, 8-15 r0-7 hi, 16-23 r8-15 lo, 24-31 r8-15 hi
            int row = ((lane >> 4) << 3) + (lane & 7);
            int ch = 2 * kc + ((lane >> 3) & 1);
            ldsm4(bk[0], bk[1], bk[2], bk[3], kb + row * 128 + ((ch ^ (row & 7)) << 4));
        }
        mma16816(S0, aq, bk[0], bk[1], S0[0], S0[1], S0[2], S0[3]);
        mma16816(S1, aq, bk[2], bk[3], S1[0], S1[1], S1[2], S1[3]);
    }

    // ---- reweight + causal mask, cvt to fp16 A-fragment ----
    __half2 ah0 = __floats2half2_rn(S0[0] * coef[0][0], S0[1] * coef[0][1]);
    __half2 ah1 = __floats2half2_rn(S0[2] * coef[1][0], S0[3] * coef[1][1]);
    __half2 ah2 = __floats2half2_rn(S1[0] * coef[0][2], S1[1] * coef[0][3]);
    __half2 ah3 = __floats2half2_rn(S1[2] * coef[1][2], S1[3] * coef[1][3]);
    u32 sa[4] = { h2u(ah0), h2u(ah1), h2u(ah2), h2u(ah3) };

    // ---- denominators (consistent with rounded numerator weights) ----
    float2 f0 = __half22float2(ah0), f2 = __half22float2(ah2);
    float2 f1 = __half22float2(ah1), f3 = __half22float2(ah3);
    float dn0 = (f0.x + f0.y) + (f2.x + f2.y);
    float dn1 = (f1.x + f1.y) + (f3.x + f3.y);
    dn0 += shxor(dn0, 1); dn0 += shxor(dn0, 2);
    dn1 += shxor(dn1, 1); dn1 += shxor(dn1, 2);
    float rd0 = __fdividef(1.f, fmaxf(dn0, EPS));
    float rd1 = __fdividef(1.f, fmaxf(dn1, EPS));

    // ---- O = S' V over 8 n-tiles, V fragments loaded per pair ----
    float* ob = out + base;
    #pragma unroll
    for (int p = 0; p < 4; ++p) {
        u32 t0, t1, t2, t3;
        {
            int row = lane & 15;
            int ch = 2 * p + (lane >> 4);
            ldsm4t(t0, t1, t2, t3, vb + row * 128 + ((ch ^ (row & 7)) << 4));
        }
        #pragma unroll
        for (int h = 0; h < 2; ++h) {
            float O[4];
            u32 b0 = h ? t2 : t0, b1 = h ? t3 : t1;
            mma16816(O, sa, b0, b1, 0.f, 0.f, 0.f, 0.f);
            int col = (2 * p + h) * 8 + jb;
            float2 lo; lo.x = O[0] * rd0; lo.y = O[1] * rd0;
            *(float2*)&ob[r0 * 64 + col] = lo;
            if (r0 != 7) {   // row r0+8 == 15 is padding
                float2 hi; hi.x = O[2] * rd1; hi.y = O[3] * rd1;
                *(float2*)&ob[(r0 + 8) * 64 + col] = hi;
            }
        }
    }
}

extern "C" void kernel_launch(void* const* d_in, const int* in_sizes, int n_in,
                              void* d_out, int out_size) {
    const float* q = (const float*)d_in[0];
    const float* k = (const float*)d_in[1];
    const float* v = (const float*)d_in[2];
    float* out = (float*)d_out;

    int n = in_sizes[0];            // B*H*L*D
    int G = n / (W * DIM);          // number of attention blocks (20480)
    int grid = (G + BLK_PER_CTA - 1) / BLK_PER_CTA;
    robust_attn_kernel<<<grid, NTHREADS>>>(q, k, v, out, G);
}

// round 15
// speedup vs baseline: 1.2468x; 1.2468x over previous
#include <cuda_runtime.h>
#include <cuda_fp16.h>

#define W 15
#define DIM 64
#define BLK_PER_CTA 4
#define NTHREADS 128
#define EPS 1e-6f
#define PHI 0.10471975511965977f   // pi/30

typedef unsigned int u32;

__device__ __forceinline__ float shxor(float v, int m) {
    return __shfl_xor_sync(0xffffffffu, v, m, 32);
}
__device__ __forceinline__ u32 smem_u32(const void* p) {
    return (u32)__cvta_generic_to_shared(p);
}
__device__ __forceinline__ void ldsm4(u32& r0, u32& r1, u32& r2, u32& r3, u32 a) {
    asm volatile("ldmatrix.sync.aligned.m8n8.x4.shared.b16 {%0,%1,%2,%3}, [%4];"
        : "=r"(r0), "=r"(r1), "=r"(r2), "=r"(r3) : "r"(a));
}
__device__ __forceinline__ void ldsm4t(u32& r0, u32& r1, u32& r2, u32& r3, u32 a) {
    asm volatile("ldmatrix.sync.aligned.m8n8.x4.trans.shared.b16 {%0,%1,%2,%3}, [%4];"
        : "=r"(r0), "=r"(r1), "=r"(r2), "=r"(r3) : "r"(a));
}
__device__ __forceinline__ void mma16816(float* d, const u32* a, u32 b0, u32 b1,
                                         float c0, float c1, float c2, float c3) {
    asm volatile(
        "mma.sync.aligned.m16n8k16.row.col.f32.f16.f16.f32 "
        "{%0,%1,%2,%3},{%4,%5,%6,%7},{%8,%9},{%10,%11,%12,%13};"
        : "=f"(d[0]), "=f"(d[1]), "=f"(d[2]), "=f"(d[3])
        : "r"(a[0]), "r"(a[1]), "r"(a[2]), "r"(a[3]), "r"(b0), "r"(b1),
          "f"(c0), "f"(c1), "f"(c2), "f"(c3));
}
__device__ __forceinline__ u32 h2u(__half2 h) { return *(u32*)&h; }

__global__ void __launch_bounds__(NTHREADS, 6)
robust_attn_kernel(const float* __restrict__ q, const float* __restrict__ k,
                   const float* __restrict__ v, float* __restrict__ out, int G)
{
    // per-warp fp16 tiles, 16 rows x 64 halfs (row 15 zeroed), XOR-swizzled
    __shared__ __align__(16) unsigned short sQ[BLK_PER_CTA][1024];
    __shared__ __align__(16) unsigned short sK[BLK_PER_CTA][1024];
    __shared__ __align__(16) unsigned short sV[BLK_PER_CTA][1024];

    const int tid = threadIdx.x;
    const int warp = tid >> 5;
    const int lane = tid & 31;
    const int blk = blockIdx.x * BLK_PER_CTA + warp;
    if (blk >= G) return;
    const size_t base = (size_t)blk * (W * DIM);

    unsigned short* wQ = sQ[warp];
    unsigned short* wK = sK[warp];
    unsigned short* wV = sV[warp];

    // ---- zero pad row 15 ----
    if (lane < 16) {
        uint2 z = make_uint2(0u, 0u);
        *(uint2*)&wQ[15 * 64 + lane * 4] = z;
        *(uint2*)&wK[15 * 64 + lane * 4] = z;
        *(uint2*)&wV[15 * 64 + lane * 4] = z;
    }

    // ---- fill: all 24 LDG.128 issued up-front (single fill latency) ----
    {
        const float4* gq = (const float4*)(q + base);
        const float4* gk = (const float4*)(k + base);
        const float4* gv = (const float4*)(v + base);
        float4 tq[8], tk[8], tv[8];
        #pragma unroll
        for (int it = 0; it < 8; ++it) {
            int i4 = it * 32 + lane;
            bool ok = (it < 7) || (lane < 16);
            if (ok) { tq[it] = gq[i4]; tk[it] = gk[i4]; tv[it] = gv[i4]; }
        }
        #pragma unroll
        for (int it = 0; it < 8; ++it) {
            int i4 = it * 32 + lane;
            bool ok = (it < 7) || (lane < 16);
            if (ok) {
                int r = i4 >> 4, cc = i4 & 15;
                int off = r * 64 + (((cc >> 1) ^ (r & 7)) << 3) + ((cc & 1) << 2);
                float4 a = tq[it];
                uint2 pa;
                pa.x = h2u(__floats2half2_rn(fmaxf(a.x, 0.f), fmaxf(a.y, 0.f)));
                pa.y = h2u(__floats2half2_rn(fmaxf(a.z, 0.f), fmaxf(a.w, 0.f)));
                *(uint2*)&wQ[off] = pa;
                float4 b = tk[it];
                uint2 pb;
                pb.x = h2u(__floats2half2_rn(fmaxf(b.x, 0.f), fmaxf(b.y, 0.f)));
                pb.y = h2u(__floats2half2_rn(fmaxf(b.z, 0.f), fmaxf(b.w, 0.f)));
                *(uint2*)&wK[off] = pb;
                float4 c = tv[it];
                uint2 pc;
                pc.x = h2u(__floats2half2_rn(fmaxf(c.x, 0.f), fmaxf(c.y, 0.f)));
                pc.y = h2u(__floats2half2_rn(fmaxf(c.z, 0.f), fmaxf(c.w, 0.f)));
                *(uint2*)&wV[off] = pc;
            }
        }
    }

    // ---- per-lane reweight constants (zero encodes causality & j=15 pad) ----
    const int r0 = lane >> 2;
    const int jb = (lane & 3) * 2;
    float coef[2][4];
    #pragma unroll
    for (int rh = 0; rh < 2; ++rh) {
        int i = r0 + rh * 8;
        #pragma unroll
        for (int jj = 0; jj < 4; ++jj) {
            int j = jb + (jj & 1) + (jj >> 1) * 8;
            int dlt = i - j;
            coef[rh][jj] = (dlt >= 0 && j < W) ? __cosf((float)dlt * PHI) : 0.f;
        }
    }

    __syncwarp();

    const u32 qb = smem_u32(wQ), kb = smem_u32(wK), vb = smem_u32(wV);

    // ---- scores: S(16x16) = Q K^T, two n8 tiles, f32 accum ----
    float S0[4] = {0.f, 0.f, 0.f, 0.f};
    float S1[4] = {0.f, 0.f, 0.f, 0.f};
    #pragma unroll
    for (int kc = 0; kc < 4; ++kc) {
        u32 aq[4], bk[4];
        {   // A: lanes 0-15 rows 0-15 chunk 2kc; lanes 16-31 chunk 2kc+1
            int row = lane & 15;
            int ch = 2 * kc + (lane >> 4);
            ldsm4(aq[0], aq[1], aq[2], aq[3], qb + row * 128 + ((ch ^ (row & 7)) << 4));
        }
        {   // B(K): lanes 0-7 r0-7 lo, 8-15 r0-7 hi, 16-23 r8-15 lo, 24-31 r8-15 hi
            int row = ((lane >> 4) << 3) + (lane & 7);
            int ch = 2 * kc + ((lane >> 3) & 1);
            ldsm4(bk[0], bk[1], bk[2], bk[3], kb + row * 128 + ((ch ^ (row & 7)) << 4));
        }
        mma16816(S0, aq, bk[0], bk[1], S0[0], S0[1], S0[2], S0[3]);
        mma16816(S1, aq, bk[2], bk[3], S1[0], S1[1], S1[2], S1[3]);
    }

    // ---- reweight + causal mask, cvt to fp16 A-fragment ----
    __half2 ah0 = __floats2half2_rn(S0[0] * coef[0][0], S0[1] * coef[0][1]);
    __half2 ah1 = __floats2half2_rn(S0[2] * coef[1][0], S0[3] * coef[1][1]);
    __half2 ah2 = __floats2half2_rn(S1[0] * coef[0][2], S1[1] * coef[0][3]);
    __half2 ah3 = __floats2half2_rn(S1[2] * coef[1][2], S1[3] * coef[1][3]);
    u32 sa[4] = { h2u(ah0), h2u(ah1), h2u(ah2), h2u(ah3) };

    // ---- denominators (consistent with rounded numerator weights) ----
    float2 f0 = __half22float2(ah0), f2 = __half22float2(ah2);
    float2 f1 = __half22float2(ah1), f3 = __half22float2(ah3);
    float dn0 = (f0.x + f0.y) + (f2.x + f2.y);
    float dn1 = (f1.x + f1.y) + (f3.x + f3.y);
    dn0 += shxor(dn0, 1); dn0 += shxor(dn0, 2);
    dn1 += shxor(dn1, 1); dn1 += shxor(dn1, 2);
    float rd0 = __fdividef(1.f, fmaxf(dn0, EPS));
    float rd1 = __fdividef(1.f, fmaxf(dn1, EPS));

    // ---- O = S' V over 8 n-tiles, V fragments loaded per pair ----
    float* ob = out + base;
    #pragma unroll
    for (int p = 0; p < 4; ++p) {
        u32 t0, t1, t2, t3;
        {
            int row = lane & 15;
            int ch = 2 * p + (lane >> 4);
            ldsm4t(t0, t1, t2, t3, vb + row * 128 + ((ch ^ (row & 7)) << 4));
        }
        #pragma unroll
        for (int h = 0; h < 2; ++h) {
            float O[4];
            u32 b0 = h ? t2 : t0, b1 = h ? t3 : t1;
            mma16816(O, sa, b0, b1, 0.f, 0.f, 0.f, 0.f);
            int col = (2 * p + h) * 8 + jb;
            float2 lo; lo.x = O[0] * rd0; lo.y = O[1] * rd0;
            *(float2*)&ob[r0 * 64 + col] = lo;
            if (r0 != 7) {   // row r0+8 == 15 is padding
                float2 hi; hi.x = O[2] * rd1; hi.y = O[3] * rd1;
                *(float2*)&ob[(r0 + 8) * 64 + col] = hi;
            }
        }
    }
}

extern "C" void kernel_launch(void* const* d_in, const int* in_sizes, int n_in,
                              void* d_out, int out_size) {
    const float* q = (const float*)d_in[0];
    const float* k = (const float*)d_in[1];
    const float* v = (const float*)d_in[2];
    float* out = (float*)d_out;

    int n = in_sizes[0];            // B*H*L*D
    int G = n / (W * DIM);          // number of attention blocks (20480)
    int grid = (G + BLK_PER_CTA - 1) / BLK_PER_CTA;
    robust_attn_kernel<<<grid, NTHREADS>>>(q, k, v, out, G);
}